// round 1
// baseline (speedup 1.0000x reference)
#include <cuda_runtime.h>
#include <cstdint>

#define N_NODES 207
#define N_EDGES 1722
#define N_SLOTS 288
#define LDIM    64
#define BATCH   1024
#define ADJ_LEN (2 * N_EDGES)   // 3444

// ---------------- device-global CSR scratch (no allocs allowed) ------------
__device__ int g_rowptr[N_NODES + 1];
__device__ int g_adj[ADJ_LEN];   // packed: (edge_idx << 8) | neighbor_node

// ---------------- setup kernel: deterministic CSR build --------------------
// Single block. Counting via smem atomics (order-independent), serial scan,
// then a DETERMINISTIC per-node scatter (each node scans edges in order) so
// the fp32 accumulation order in the main kernel is identical every call.
__global__ void build_csr_kernel(const int* __restrict__ edge_i,
                                 const int* __restrict__ edge_j) {
    __shared__ int s_ei[N_EDGES];
    __shared__ int s_ej[N_EDGES];
    __shared__ int s_cnt[N_NODES + 1];
    const int tid = threadIdx.x;

    for (int e = tid; e < N_EDGES; e += blockDim.x) {
        s_ei[e] = edge_i[e];
        s_ej[e] = edge_j[e];
    }
    for (int v = tid; v < N_NODES + 1; v += blockDim.x) s_cnt[v] = 0;
    __syncthreads();

    for (int e = tid; e < N_EDGES; e += blockDim.x) {
        atomicAdd(&s_cnt[s_ei[e]], 1);
        atomicAdd(&s_cnt[s_ej[e]], 1);
    }
    __syncthreads();

    if (tid == 0) {
        int run = 0;
        for (int v = 0; v < N_NODES; v++) {
            int c = s_cnt[v];
            s_cnt[v] = run;          // becomes start offset
            g_rowptr[v] = run;
            run += c;
        }
        g_rowptr[N_NODES] = run;     // == ADJ_LEN
    }
    __syncthreads();

    // deterministic scatter: one thread owns one node, scans edges in order
    for (int v = tid; v < N_NODES; v += blockDim.x) {
        int pos = s_cnt[v];
        for (int e = 0; e < N_EDGES; e++) {
            if (s_ei[e] == v) g_adj[pos++] = (e << 8) | s_ej[e];
            if (s_ej[e] == v) g_adj[pos++] = (e << 8) | s_ei[e];
        }
    }
}

// ---------------- main kernel: one CTA per batch element -------------------
// smem: x tile (fp32, 207x64), weight row, wsl/bias rows, CSR copy.
// Each warp owns output nodes w (strided); lane handles columns {2*lane, 2*lane+1}
// as a float2. All gather LDS are conflict-free (consecutive float2 per lane);
// adjacency/weight LDS are warp-uniform broadcasts. Accumulation entirely in
// registers -> zero atomics, zero extra smem traffic for the accumulator.
__global__ __launch_bounds__(256, 2)
void diffusion_gcn_kernel(const float*  __restrict__ inputs,      // (B,2,N,L)
                          const float*  __restrict__ weight_diff, // (S,E)
                          const float*  __restrict__ bias_diff,   // (S,N)
                          const float*  __restrict__ weight_sl,   // (S,N)
                          const int*    __restrict__ ind,         // (B,)
                          float*        __restrict__ out)         // (B,N,L)
{
    extern __shared__ float smem[];
    float* s_x    = smem;                       // 207*64 = 13248
    float* s_w    = s_x + N_NODES * LDIM;       // 1722
    float* s_wsl  = s_w + N_EDGES;              // 207
    float* s_bias = s_wsl + N_NODES;            // 207
    int*   s_rowp = (int*)(s_bias + N_NODES);   // 208
    int*   s_adj  = s_rowp + (N_NODES + 1);     // 3444

    const int b   = blockIdx.x;
    const int tid = threadIdx.x;
    const int slot = ind[b];                    // uniform -> broadcast load

    // ---- stage: fill shared memory -----------------------------------
    {   // x = inputs[b, 0, :, :] : 13248 floats = 3312 float4, coalesced
        const float4* src = (const float4*)(inputs + (size_t)b * 2 * N_NODES * LDIM);
        float4* dst = (float4*)s_x;
        #pragma unroll 4
        for (int i = tid; i < (N_NODES * LDIM) / 4; i += 256) dst[i] = src[i];
    }
    {
        const float* wrow = weight_diff + (size_t)slot * N_EDGES;
        for (int i = tid; i < N_EDGES; i += 256) s_w[i] = wrow[i];
    }
    for (int i = tid; i < N_NODES; i += 256) {
        s_wsl[i]  = weight_sl[(size_t)slot * N_NODES + i];
        s_bias[i] = bias_diff[(size_t)slot * N_NODES + i];
    }
    for (int i = tid; i < N_NODES + 1; i += 256) s_rowp[i] = g_rowptr[i];
    for (int i = tid; i < ADJ_LEN; i += 256)     s_adj[i]  = g_adj[i];
    __syncthreads();

    // ---- stage: per-node gather --------------------------------------
    const int warp = tid >> 5;
    const int lane = tid & 31;

    for (int w = warp; w < N_NODES; w += 8) {
        const int beg = s_rowp[w];
        const int end = s_rowp[w + 1];
        float accx = 0.0f, accy = 0.0f, deg = 0.0f;

        int t = beg;
        // unroll-by-2 for LDS latency overlap
        for (; t + 1 < end; t += 2) {
            const int p0 = s_adj[t];
            const int p1 = s_adj[t + 1];
            const float we0 = s_w[p0 >> 8];
            const float we1 = s_w[p1 >> 8];
            const float2 x0 = *(const float2*)(s_x + (p0 & 255) * LDIM + 2 * lane);
            const float2 x1 = *(const float2*)(s_x + (p1 & 255) * LDIM + 2 * lane);
            deg += we0 + we1;
            accx = fmaf(-we0, x0.x, accx);
            accy = fmaf(-we0, x0.y, accy);
            accx = fmaf(-we1, x1.x, accx);
            accy = fmaf(-we1, x1.y, accy);
        }
        if (t < end) {
            const int p = s_adj[t];
            const float we = s_w[p >> 8];
            const float2 xu = *(const float2*)(s_x + (p & 255) * LDIM + 2 * lane);
            deg += we;
            accx = fmaf(-we, xu.x, accx);
            accy = fmaf(-we, xu.y, accy);
        }

        const float2 xw = *(const float2*)(s_x + w * LDIM + 2 * lane);
        const float scale = deg + 1.0f + s_wsl[w];
        const float bi = s_bias[w];
        float2 o;
        o.x = fmaf(scale, xw.x, bi + accx);
        o.y = fmaf(scale, xw.y, bi + accy);
        *(float2*)(out + ((size_t)b * N_NODES + w) * LDIM + 2 * lane) = o;
    }
}

// ---------------- launcher ---------------------------------------------
extern "C" void kernel_launch(void* const* d_in, const int* in_sizes, int n_in,
                              void* d_out, int out_size) {
    const float* inputs      = (const float*)d_in[0];
    const float* weight_diff = (const float*)d_in[1];
    const float* bias_diff   = (const float*)d_in[2];
    const float* weight_sl   = (const float*)d_in[3];
    const int*   ind         = (const int*)d_in[4];
    const int*   edge_i      = (const int*)d_in[5];
    const int*   edge_j      = (const int*)d_in[6];
    float*       out         = (float*)d_out;

    const int smem_bytes =
        (N_NODES * LDIM + N_EDGES + 2 * N_NODES) * (int)sizeof(float) +
        (N_NODES + 1 + ADJ_LEN) * (int)sizeof(int);

    static bool attr_set = false;   // host-side config only, not a work guard
    if (!attr_set) {
        cudaFuncSetAttribute(diffusion_gcn_kernel,
                             cudaFuncAttributeMaxDynamicSharedMemorySize,
                             smem_bytes);
        attr_set = true;
    }

    build_csr_kernel<<<1, 256>>>(edge_i, edge_j);
    diffusion_gcn_kernel<<<BATCH, 256, smem_bytes>>>(
        inputs, weight_diff, bias_diff, weight_sl, ind, out);
}

// round 2
// speedup vs baseline: 1.1680x; 1.1680x over previous
#include <cuda_runtime.h>
#include <cstdint>

#define N_NODES 207
#define N_EDGES 1722
#define N_SLOTS 288
#define LDIM    64
#define BATCH   1024
#define ADJ_CAP 4096            // padded adjacency capacity (>= 3444 + 207*3, pow2)

// ---------------- device-global CSR scratch (no allocs allowed) ------------
__device__ int g_rowptr4[N_NODES + 1];                       // 4-aligned starts
__device__ __align__(16) unsigned short g_adj_node[ADJ_CAP]; // neighbor*64 (smem float offset)
__device__ __align__(16) unsigned short g_adj_edge[ADJ_CAP]; // edge idx; N_EDGES = dummy (weight 0)

// ---------------- setup kernel: fast deterministic padded-CSR build --------
// Counting via smem atomics (order-independent -> deterministic counts),
// serial 207-scan for rowptr, then a SINGLE-WARP scatter using
// __match_any_sync ballot ranking: groups of 32 entries processed in order,
// rank within group = lane order => global order per node = entry idx
// ascending, fully deterministic. ~3.5k warp-iterations total.
__global__ void build_csr_kernel(const int* __restrict__ edge_i,
                                 const int* __restrict__ edge_j) {
    __shared__ int s_ei[N_EDGES];
    __shared__ int s_ej[N_EDGES];
    __shared__ int s_tot[N_NODES];
    __shared__ int s_off[N_NODES];
    const int tid = threadIdx.x;

    for (int i = tid; i < N_EDGES; i += blockDim.x) {
        s_ei[i] = edge_i[i];
        s_ej[i] = edge_j[i];
    }
    for (int v = tid; v < N_NODES; v += blockDim.x) s_tot[v] = 0;
    // dummy-fill the padded global arrays (overwritten where real entries land)
    for (int t = tid; t < ADJ_CAP; t += blockDim.x) {
        g_adj_node[t] = 0;
        g_adj_edge[t] = (unsigned short)N_EDGES;   // weight slot forced to 0
    }
    __syncthreads();

    for (int idx = tid; idx < 2 * N_EDGES; idx += blockDim.x) {
        const int e = idx >> 1;
        const int v = (idx & 1) ? s_ej[e] : s_ei[e];
        atomicAdd(&s_tot[v], 1);
    }
    __syncthreads();

    if (tid == 0) {
        int run = 0;
        for (int v = 0; v < N_NODES; v++) {
            s_off[v] = run;
            g_rowptr4[v] = run;
            run += (s_tot[v] + 3) & ~3;            // pad to multiple of 4
        }
        g_rowptr4[N_NODES] = run;
    }
    __syncthreads();

    if (tid < 32) {
        const int lane = tid;
        const int ngroups = (2 * N_EDGES + 31) / 32;
        for (int g = 0; g < ngroups; ++g) {
            const int idx = g * 32 + lane;
            const bool valid = idx < 2 * N_EDGES;
            int v, nbr = 0, e = idx >> 1;
            if (valid) {
                if (idx & 1) { v = s_ej[e]; nbr = s_ei[e]; }
                else         { v = s_ei[e]; nbr = s_ej[e]; }
            } else {
                v = N_NODES + lane;                // unique fake id, no store
            }
            const unsigned mask = __match_any_sync(0xffffffffu, v);
            const int rank = __popc(mask & ((1u << lane) - 1u));
            int base = 0;
            if (valid) base = s_off[v];            // pre-update value for group
            __syncwarp();
            if (valid && lane == (__ffs(mask) - 1))
                s_off[v] = base + __popc(mask);
            __syncwarp();
            if (valid) {
                const int pos = base + rank;
                g_adj_node[pos] = (unsigned short)(nbr * LDIM);
                g_adj_edge[pos] = (unsigned short)e;
            }
        }
    }
}

// ---------------- main kernel: one CTA per batch element -------------------
// smem float layout (floats):
//   s_x    [13248]  x tile (207 x 64)
//   s_wadj [4096]   weights expanded to adjacency order (float4-readable)
//   s_w    [1728]   slot weight row (+ zero dummy at [1722..])
//   s_wsl  [208], s_bias [208]
// then int s_rowp[208], then u16 s_adjn[4096].
// Each warp owns TWO nodes per pass: lanes 0-15 -> node A, lanes 16-31 ->
// node B; each lane holds 4 columns (float4) => a half-warp covers the full
// 64-column row. Adjacency consumed 4 entries at a time (ushort4 offsets +
// float4 weights) => ~0.3 scalar wavefronts per entry instead of 2.
#define S_X_F     0
#define S_WADJ_F  13248
#define S_W_F     17344
#define S_WSL_F   19072
#define S_BIAS_F  19280
#define S_ROWP_B  77952
#define S_ADJN_B  78784
#define SMEM_BYTES 86976

__global__ __launch_bounds__(256, 2)
void diffusion_gcn_kernel(const float*  __restrict__ inputs,      // (B,2,N,L)
                          const float*  __restrict__ weight_diff, // (S,E)
                          const float*  __restrict__ bias_diff,   // (S,N)
                          const float*  __restrict__ weight_sl,   // (S,N)
                          const int*    __restrict__ ind,         // (B,)
                          float*        __restrict__ out)         // (B,N,L)
{
    extern __shared__ char smem[];
    float* s_x    = (float*)smem + S_X_F;
    float* s_wadj = (float*)smem + S_WADJ_F;
    float* s_w    = (float*)smem + S_W_F;
    float* s_wsl  = (float*)smem + S_WSL_F;
    float* s_bias = (float*)smem + S_BIAS_F;
    int*   s_rowp = (int*)(smem + S_ROWP_B);
    unsigned short* s_adjn = (unsigned short*)(smem + S_ADJN_B);

    const int b    = blockIdx.x;
    const int tid  = threadIdx.x;
    const int slot = ind[b];

    // ---- phase A: fill smem (everything except s_wadj) -----------------
    {   // x = inputs[b, 0, :, :] : 3312 float4, coalesced
        const float4* src = (const float4*)(inputs + (size_t)b * 2 * N_NODES * LDIM);
        float4* dst = (float4*)s_x;
        #pragma unroll 4
        for (int i = tid; i < (N_NODES * LDIM) / 4; i += 256) dst[i] = src[i];
    }
    {
        const float* wrow = weight_diff + (size_t)slot * N_EDGES;
        for (int i = tid; i < 1728; i += 256)
            s_w[i] = (i < N_EDGES) ? wrow[i] : 0.0f;
    }
    for (int i = tid; i < N_NODES; i += 256) {
        s_wsl[i]  = weight_sl[(size_t)slot * N_NODES + i];
        s_bias[i] = bias_diff[(size_t)slot * N_NODES + i];
    }
    for (int i = tid; i < N_NODES + 1; i += 256) s_rowp[i] = g_rowptr4[i];
    {   // adjacency offsets: 8192 B as 512 uint4
        const uint4* src = (const uint4*)g_adj_node;
        uint4* dst = (uint4*)s_adjn;
        for (int i = tid; i < ADJ_CAP / 8; i += 256) dst[i] = src[i];
    }
    __syncthreads();

    // ---- phase B: expand weights into adjacency order ------------------
    for (int t = tid; t < ADJ_CAP; t += 256)
        s_wadj[t] = s_w[(int)g_adj_edge[t]];
    __syncthreads();

    // ---- phase C: gather ------------------------------------------------
    const int warp = tid >> 5;
    const int lane = tid & 31;
    const int half = lane >> 4;          // 0: node A, 1: node B
    const int hl   = lane & 15;          // lane within half (column group)

    #pragma unroll 1
    for (int pass = 0; pass < 13; ++pass) {
        const int w  = pass * 16 + warp * 2 + half;   // 13*16 = 208 slots
        const bool vn = (w < N_NODES);
        const int beg = vn ? s_rowp[w] : 0;
        const int ng  = vn ? ((s_rowp[w + 1] - beg) >> 2) : 0;
        const int ngo = __shfl_xor_sync(0xffffffffu, ng, 16);
        const int ngmax = ng > ngo ? ng : ngo;

        float ax = 0.f, ay = 0.f, az = 0.f, aw = 0.f, deg = 0.f;

        for (int g = 0; g < ngmax; ++g) {
            const bool gv = (g < ng);
            const int t = beg + ((gv ? g : 0) << 2);
            ushort4 of = *(const ushort4*)(s_adjn + t);
            float4  wq = *(const float4*)(s_wadj + t);
            if (!gv) { wq.x = 0.f; wq.y = 0.f; wq.z = 0.f; wq.w = 0.f; }

            float4 xv;
            xv = *(const float4*)(s_x + of.x + 4 * hl);
            deg += wq.x;
            ax = fmaf(-wq.x, xv.x, ax); ay = fmaf(-wq.x, xv.y, ay);
            az = fmaf(-wq.x, xv.z, az); aw = fmaf(-wq.x, xv.w, aw);

            xv = *(const float4*)(s_x + of.y + 4 * hl);
            deg += wq.y;
            ax = fmaf(-wq.y, xv.x, ax); ay = fmaf(-wq.y, xv.y, ay);
            az = fmaf(-wq.y, xv.z, az); aw = fmaf(-wq.y, xv.w, aw);

            xv = *(const float4*)(s_x + of.z + 4 * hl);
            deg += wq.z;
            ax = fmaf(-wq.z, xv.x, ax); ay = fmaf(-wq.z, xv.y, ay);
            az = fmaf(-wq.z, xv.z, az); aw = fmaf(-wq.z, xv.w, aw);

            xv = *(const float4*)(s_x + of.w + 4 * hl);
            deg += wq.w;
            ax = fmaf(-wq.w, xv.x, ax); ay = fmaf(-wq.w, xv.y, ay);
            az = fmaf(-wq.w, xv.z, az); aw = fmaf(-wq.w, xv.w, aw);
        }

        if (vn) {
            const float4 xw = *(const float4*)(s_x + w * LDIM + 4 * hl);
            const float sc = deg + 1.0f + s_wsl[w];
            const float bi = s_bias[w];
            float4 o;
            o.x = fmaf(sc, xw.x, bi + ax);
            o.y = fmaf(sc, xw.y, bi + ay);
            o.z = fmaf(sc, xw.z, bi + az);
            o.w = fmaf(sc, xw.w, bi + aw);
            *(float4*)(out + ((size_t)b * N_NODES + w) * LDIM + 4 * hl) = o;
        }
    }
}

// ---------------- launcher ---------------------------------------------
extern "C" void kernel_launch(void* const* d_in, const int* in_sizes, int n_in,
                              void* d_out, int out_size) {
    const float* inputs      = (const float*)d_in[0];
    const float* weight_diff = (const float*)d_in[1];
    const float* bias_diff   = (const float*)d_in[2];
    const float* weight_sl   = (const float*)d_in[3];
    const int*   ind         = (const int*)d_in[4];
    const int*   edge_i      = (const int*)d_in[5];
    const int*   edge_j      = (const int*)d_in[6];
    float*       out         = (float*)d_out;

    static bool attr_set = false;   // host-side config only, not a work guard
    if (!attr_set) {
        cudaFuncSetAttribute(diffusion_gcn_kernel,
                             cudaFuncAttributeMaxDynamicSharedMemorySize,
                             SMEM_BYTES);
        attr_set = true;
    }

    build_csr_kernel<<<1, 1024>>>(edge_i, edge_j);
    diffusion_gcn_kernel<<<BATCH, 256, SMEM_BYTES>>>(
        inputs, weight_diff, bias_diff, weight_sl, ind, out);
}

// round 3
// speedup vs baseline: 1.6348x; 1.3996x over previous
#include <cuda_runtime.h>
#include <cstdint>

#define N_NODES 207
#define N_EDGES 1722
#define N_SLOTS 288
#define LDIM    64
#define BATCH   1024
#define ADJ_CAP 4096            // padded adjacency capacity (3444 + pad <= 4065)

// ---------------- device-global CSR scratch (no allocs allowed) ------------
__device__ int g_rowptr4[N_NODES + 1];                       // 4-aligned starts
__device__ __align__(16) unsigned short g_adj_node[ADJ_CAP]; // neighbor*64 (smem float offset)
__device__ __align__(16) unsigned short g_adj_edge[ADJ_CAP]; // edge idx; N_EDGES = dummy (weight 0)

// ---------------- setup kernel: parallel deterministic padded-CSR ----------
// 1024 threads. Entries idx = 0..2E-1 (idx=2e -> (i[e] gets j[e]), idx=2e+1 ->
// (j[e] gets i[e])). Final order within each node's list = ascending idx,
// which is fully deterministic. Implementation: process entries in 4 chunks
// of 1024; within a chunk each warp ballot-ranks duplicates via
// __match_any_sync, leaders record per-(warp,node) counts, a per-node
// cross-warp exclusive scan turns them into bases, then everyone scatters.
__global__ __launch_bounds__(1024, 1)
void build_csr_kernel(const int* __restrict__ edge_i,
                      const int* __restrict__ edge_j) {
    __shared__ int s_ei[N_EDGES];
    __shared__ int s_ej[N_EDGES];
    __shared__ int s_off[N_NODES + 1];
    __shared__ int s_wcnt[32][N_NODES + 1];   // count -> base, per warp
    const int tid  = threadIdx.x;
    const int warp = tid >> 5;
    const int lane = tid & 31;

    for (int i = tid; i < N_EDGES; i += 1024) {
        s_ei[i] = edge_i[i];
        s_ej[i] = edge_j[i];
    }
    for (int v = tid; v < N_NODES + 1; v += 1024) s_off[v] = 0;
    for (int t = tid; t < ADJ_CAP; t += 1024) {
        g_adj_node[t] = 0;
        g_adj_edge[t] = (unsigned short)N_EDGES;   // dummy -> weight 0
    }
    __syncthreads();

    // degree count (order-independent)
    for (int idx = tid; idx < 2 * N_EDGES; idx += 1024) {
        const int e = idx >> 1;
        const int v = (idx & 1) ? s_ej[e] : s_ei[e];
        atomicAdd(&s_off[v], 1);
    }
    __syncthreads();

    // exclusive scan with pad-to-4 (serial, 207 iters, cheap)
    if (tid == 0) {
        int run = 0;
        for (int v = 0; v < N_NODES; v++) {
            const int c = s_off[v];
            s_off[v] = run;
            g_rowptr4[v] = run;
            run += (c + 3) & ~3;
        }
        g_rowptr4[N_NODES] = run;
    }
    __syncthreads();

    // 4 chunks of 1024 entries
    #pragma unroll 1
    for (int c = 0; c < 4; ++c) {
        for (int i = tid; i < 32 * (N_NODES + 1); i += 1024)
            ((int*)s_wcnt)[i] = 0;
        __syncthreads();

        const int idx   = c * 1024 + tid;
        const bool valid = idx < 2 * N_EDGES;
        int v, nbr = 0;
        const int e = idx >> 1;
        if (valid) {
            if (idx & 1) { v = s_ej[e]; nbr = s_ei[e]; }
            else         { v = s_ei[e]; nbr = s_ej[e]; }
        } else {
            v = N_NODES;                    // shared dummy bucket (never stored)
        }
        const unsigned mask = __match_any_sync(0xffffffffu, v);
        const int rank = __popc(mask & ((1u << lane) - 1u));
        if (valid && lane == (__ffs(mask) - 1))
            s_wcnt[warp][v] = __popc(mask);
        __syncthreads();

        // per-node exclusive scan across warps; update running s_off
        if (tid < N_NODES) {
            int run = s_off[tid];
            #pragma unroll
            for (int w = 0; w < 32; ++w) {
                const int t = s_wcnt[w][tid];
                s_wcnt[w][tid] = run;
                run += t;
            }
            s_off[tid] = run;
        }
        __syncthreads();

        if (valid) {
            const int pos = s_wcnt[warp][v] + rank;
            g_adj_node[pos] = (unsigned short)(nbr * LDIM);
            g_adj_edge[pos] = (unsigned short)e;
        }
        __syncthreads();
    }
}

// ---------------- main kernel: one CTA (512 thr) per batch element ---------
// smem float layout:
//   s_x    [13248]  x tile (207 x 64)
//   s_wadj [4096]   weights expanded to adjacency order (float4-readable)
//   s_w    [1728]   slot weight row (+ zero dummies)
//   s_wsl  [208], s_bias [208]
// then int s_rowp[208], then u16 s_adjn[4096].
// Each warp owns TWO nodes per pass: lanes 0-15 -> node A, 16-31 -> node B;
// each lane covers 4 columns (float4). Adjacency consumed 4 entries/iter
// (ushort4 offsets + float4 weights) => ~1.25 wavefronts per entry.
#define S_X_F     0
#define S_WADJ_F  13248
#define S_W_F     17344
#define S_WSL_F   19072
#define S_BIAS_F  19280
#define S_ROWP_B  77952
#define S_ADJN_B  78784
#define SMEM_BYTES 86976

__global__ __launch_bounds__(512, 2)
void diffusion_gcn_kernel(const float*  __restrict__ inputs,      // (B,2,N,L)
                          const float*  __restrict__ weight_diff, // (S,E)
                          const float*  __restrict__ bias_diff,   // (S,N)
                          const float*  __restrict__ weight_sl,   // (S,N)
                          const int*    __restrict__ ind,         // (B,)
                          float*        __restrict__ out)         // (B,N,L)
{
    extern __shared__ char smem[];
    float* s_x    = (float*)smem + S_X_F;
    float* s_wadj = (float*)smem + S_WADJ_F;
    float* s_w    = (float*)smem + S_W_F;
    float* s_wsl  = (float*)smem + S_WSL_F;
    float* s_bias = (float*)smem + S_BIAS_F;
    int*   s_rowp = (int*)(smem + S_ROWP_B);
    unsigned short* s_adjn = (unsigned short*)(smem + S_ADJN_B);

    const int b    = blockIdx.x;
    const int tid  = threadIdx.x;
    const int slot = ind[b];

    // ---- phase A: stage smem -------------------------------------------
    {   // x = inputs[b, 0, :, :] : 3312 float4, coalesced
        const float4* src = (const float4*)(inputs + (size_t)b * 2 * N_NODES * LDIM);
        float4* dst = (float4*)s_x;
        #pragma unroll 4
        for (int i = tid; i < (N_NODES * LDIM) / 4; i += 512) dst[i] = src[i];
    }
    {
        const float* wrow = weight_diff + (size_t)slot * N_EDGES;
        for (int i = tid; i < 1728; i += 512)
            s_w[i] = (i < N_EDGES) ? wrow[i] : 0.0f;
    }
    for (int i = tid; i < N_NODES; i += 512) {
        s_wsl[i]  = weight_sl[(size_t)slot * N_NODES + i];
        s_bias[i] = bias_diff[(size_t)slot * N_NODES + i];
    }
    for (int i = tid; i < N_NODES + 1; i += 512) s_rowp[i] = g_rowptr4[i];
    {   // adjacency offsets: 8192 B as 512 uint4
        const uint4* src = (const uint4*)g_adj_node;
        uint4* dst = (uint4*)s_adjn;
        for (int i = tid; i < ADJ_CAP / 8; i += 512) dst[i] = src[i];
    }
    __syncthreads();

    // ---- phase B: expand weights into adjacency order -------------------
    for (int t = tid; t < ADJ_CAP; t += 512)
        s_wadj[t] = s_w[(int)g_adj_edge[t]];
    __syncthreads();

    // ---- phase C: gather -------------------------------------------------
    const int warp = tid >> 5;           // 0..15
    const int lane = tid & 31;
    const int half = lane >> 4;          // 0: node A, 1: node B
    const int hl   = lane & 15;          // column group within half

    #pragma unroll 1
    for (int pass = 0; pass < 7; ++pass) {
        const int w  = pass * 32 + warp * 2 + half;   // 7*32 = 224 slots
        const bool vn = (w < N_NODES);
        const int beg = vn ? s_rowp[w] : 0;
        const int ng  = vn ? ((s_rowp[w + 1] - beg) >> 2) : 0;
        const int ngo = __shfl_xor_sync(0xffffffffu, ng, 16);
        const int ngmax = ng > ngo ? ng : ngo;

        float ax = 0.f, ay = 0.f, az = 0.f, aw = 0.f, deg = 0.f;

        #pragma unroll 1
        for (int g = 0; g < ngmax; ++g) {
            const bool gv = (g < ng);
            const int t = beg + ((gv ? g : 0) << 2);
            ushort4 of = *(const ushort4*)(s_adjn + t);
            float4  wq = *(const float4*)(s_wadj + t);
            if (!gv) { wq.x = 0.f; wq.y = 0.f; wq.z = 0.f; wq.w = 0.f; }

            float4 xv;
            xv = *(const float4*)(s_x + of.x + 4 * hl);
            deg += wq.x;
            ax = fmaf(-wq.x, xv.x, ax); ay = fmaf(-wq.x, xv.y, ay);
            az = fmaf(-wq.x, xv.z, az); aw = fmaf(-wq.x, xv.w, aw);

            xv = *(const float4*)(s_x + of.y + 4 * hl);
            deg += wq.y;
            ax = fmaf(-wq.y, xv.x, ax); ay = fmaf(-wq.y, xv.y, ay);
            az = fmaf(-wq.y, xv.z, az); aw = fmaf(-wq.y, xv.w, aw);

            xv = *(const float4*)(s_x + of.z + 4 * hl);
            deg += wq.z;
            ax = fmaf(-wq.z, xv.x, ax); ay = fmaf(-wq.z, xv.y, ay);
            az = fmaf(-wq.z, xv.z, az); aw = fmaf(-wq.z, xv.w, aw);

            xv = *(const float4*)(s_x + of.w + 4 * hl);
            deg += wq.w;
            ax = fmaf(-wq.w, xv.x, ax); ay = fmaf(-wq.w, xv.y, ay);
            az = fmaf(-wq.w, xv.z, az); aw = fmaf(-wq.w, xv.w, aw);
        }

        if (vn) {
            const float4 xw = *(const float4*)(s_x + w * LDIM + 4 * hl);
            const float sc = deg + 1.0f + s_wsl[w];
            const float bi = s_bias[w];
            float4 o;
            o.x = fmaf(sc, xw.x, bi + ax);
            o.y = fmaf(sc, xw.y, bi + ay);
            o.z = fmaf(sc, xw.z, bi + az);
            o.w = fmaf(sc, xw.w, bi + aw);
            *(float4*)(out + ((size_t)b * N_NODES + w) * LDIM + 4 * hl) = o;
        }
    }
}

// ---------------- launcher ---------------------------------------------
extern "C" void kernel_launch(void* const* d_in, const int* in_sizes, int n_in,
                              void* d_out, int out_size) {
    const float* inputs      = (const float*)d_in[0];
    const float* weight_diff = (const float*)d_in[1];
    const float* bias_diff   = (const float*)d_in[2];
    const float* weight_sl   = (const float*)d_in[3];
    const int*   ind         = (const int*)d_in[4];
    const int*   edge_i      = (const int*)d_in[5];
    const int*   edge_j      = (const int*)d_in[6];
    float*       out         = (float*)d_out;

    static bool attr_set = false;   // host-side config only, not a work guard
    if (!attr_set) {
        cudaFuncSetAttribute(diffusion_gcn_kernel,
                             cudaFuncAttributeMaxDynamicSharedMemorySize,
                             SMEM_BYTES);
        attr_set = true;
    }

    build_csr_kernel<<<1, 1024>>>(edge_i, edge_j);
    diffusion_gcn_kernel<<<BATCH, 512, SMEM_BYTES>>>(
        inputs, weight_diff, bias_diff, weight_sl, ind, out);
}

// round 4
// speedup vs baseline: 1.9973x; 1.2217x over previous
#include <cuda_runtime.h>
#include <cuda_bf16.h>
#include <cstdint>

#define N_NODES 207
#define N_EDGES 1722
#define LDIM    64
#define BATCH   1024
#define N_SLOTS_PAD 224          // 7 passes * 32 slots
#define ADJ_CAP 4608             // 4 * (sum ceil(deg/4)) upper bound

// ---------------- device-global CSR scratch (no allocs allowed) ------------
__device__ int g_rowptr4[N_SLOTS_PAD + 1];                   // entry start by SORTED SLOT
__device__ unsigned short g_order[N_SLOTS_PAD];              // slot -> node id (0xFFFF invalid)
__device__ __align__(16) unsigned short g_adj_node[ADJ_CAP]; // nbr*32 (u32 index of bf16 row)
__device__ __align__(16) unsigned short g_adj_edge[ADJ_CAP]; // edge idx; N_EDGES = dummy (w=0)

// ---------------- setup kernel: deterministic sorted padded-CSR ------------
// Order within each node's adjacency = ascending global entry index
// (idx = 2e -> i[e] gets j[e]; idx = 2e+1 -> j[e] gets i[e]) -> deterministic.
// Nodes are SORTED desc by ceil(deg/4) (tie: asc id); slots paired 2k/2k+1
// therefore have near-equal group counts.
__global__ __launch_bounds__(1024, 1)
void build_csr_kernel(const int* __restrict__ edge_i,
                      const int* __restrict__ edge_j) {
    __shared__ int s_ei[N_EDGES];
    __shared__ int s_ej[N_EDGES];
    __shared__ int s_ng[N_NODES];
    __shared__ int s_off[N_NODES + 1];          // deg count -> entry base
    __shared__ unsigned short s_ord[N_SLOTS_PAD];
    __shared__ int s_wcnt[32][N_NODES + 1];
    const int tid  = threadIdx.x;
    const int warp = tid >> 5;
    const int lane = tid & 31;

    for (int i = tid; i < N_EDGES; i += 1024) {
        s_ei[i] = edge_i[i];
        s_ej[i] = edge_j[i];
    }
    for (int v = tid; v < N_NODES + 1; v += 1024) s_off[v] = 0;
    for (int i = tid; i < N_SLOTS_PAD; i += 1024) s_ord[i] = 0xFFFFu;
    for (int t = tid; t < ADJ_CAP; t += 1024) {
        g_adj_node[t] = 0;
        g_adj_edge[t] = (unsigned short)N_EDGES;    // dummy -> weight 0
    }
    __syncthreads();

    // degree count (order-independent)
    for (int idx = tid; idx < 2 * N_EDGES; idx += 1024) {
        const int e = idx >> 1;
        const int v = (idx & 1) ? s_ej[e] : s_ei[e];
        atomicAdd(&s_off[v], 1);
    }
    __syncthreads();

    if (tid < N_NODES) s_ng[tid] = (s_off[tid] + 3) >> 2;
    __syncthreads();

    // parallel rank sort: desc by ng, tie asc id
    if (tid < N_NODES) {
        const int nv = s_ng[tid];
        int r = 0;
        for (int u = 0; u < N_NODES; ++u) {
            const int nu = s_ng[u];
            r += (nu > nv) || (nu == nv && u < tid);
        }
        s_ord[r] = (unsigned short)tid;
    }
    __syncthreads();

    // slot-order exclusive scan of group counts (warp 0, shuffle scan)
    if (warp == 0) {
        int carry = 0;
        #pragma unroll
        for (int c = 0; c < 7; ++c) {
            const int s = c * 32 + lane;
            const int vn = s_ord[s];
            const int p = (vn != 0xFFFF) ? s_ng[vn] : 0;
            int si = p;
            #pragma unroll
            for (int o = 1; o < 32; o <<= 1) {
                const int t = __shfl_up_sync(0xffffffffu, si, o);
                if (lane >= o) si += t;
            }
            const int excl = carry + si - p;
            g_rowptr4[s] = excl * 4;
            if (vn != 0xFFFF) s_off[vn] = excl * 4;
            carry += __shfl_sync(0xffffffffu, si, 31);
        }
        if (lane == 0) g_rowptr4[N_SLOTS_PAD] = carry * 4;
    }
    __syncthreads();
    for (int i = tid; i < N_SLOTS_PAD; i += 1024) g_order[i] = s_ord[i];

    // chunked deterministic scatter (4 chunks of 1024 entries)
    #pragma unroll 1
    for (int c = 0; c < 4; ++c) {
        for (int i = tid; i < 32 * (N_NODES + 1); i += 1024)
            ((int*)s_wcnt)[i] = 0;
        __syncthreads();

        const int idx    = c * 1024 + tid;
        const bool valid = idx < 2 * N_EDGES;
        int v, nbr = 0;
        const int e = idx >> 1;
        if (valid) {
            if (idx & 1) { v = s_ej[e]; nbr = s_ei[e]; }
            else         { v = s_ei[e]; nbr = s_ej[e]; }
        } else {
            v = N_NODES;                        // dummy bucket (never stored)
        }
        const unsigned mask = __match_any_sync(0xffffffffu, v);
        const int rank = __popc(mask & ((1u << lane) - 1u));
        if (valid && lane == (__ffs(mask) - 1))
            s_wcnt[warp][v] = __popc(mask);
        __syncthreads();

        if (tid < N_NODES) {
            int run = s_off[tid];
            #pragma unroll
            for (int w = 0; w < 32; ++w) {
                const int t = s_wcnt[w][tid];
                s_wcnt[w][tid] = run;
                run += t;
            }
            s_off[tid] = run;
        }
        __syncthreads();

        if (valid) {
            const int pos = s_wcnt[warp][v] + rank;
            g_adj_node[pos] = (unsigned short)(nbr * 32);  // u32-index of bf16 row
            g_adj_edge[pos] = (unsigned short)e;
        }
        __syncthreads();
    }
}

// ---------------- main kernel: one CTA (512 thr) per batch element ---------
// smem layout (bytes):
//   s_xh    [26496] x tile in bf16 (207 rows x 128 B)
//   s_wadj  [18432] weights in adjacency order (float4-readable)
//   s_w     [ 6912] slot weight row + zero dummy
//   s_wsl   [  832] s_bias [832]
//   s_rowp  [  912] (225 ints, padded)   s_order [448]   s_adjn [9216]
// Warp = 2 sorted slots (halves); lane covers 4 cols via 2x bf16x2.
// Diagonal term uses fp32 x prefetched from GLOBAL (L2-hot) -> full precision
// on the dominant term; bf16 only touches the small diffusion sum.
#define S_XH_B    0
#define S_WADJ_B  26496
#define S_W_B     44928
#define S_WSL_B   51840
#define S_BIAS_B  52672
#define S_ROWP_B  53504
#define S_ORD_B   54416
#define S_ADJN_B  54864
#define SMEM_BYTES 64080

__global__ __launch_bounds__(512, 3)
void diffusion_gcn_kernel(const float*  __restrict__ inputs,      // (B,2,N,L)
                          const float*  __restrict__ weight_diff, // (S,E)
                          const float*  __restrict__ bias_diff,   // (S,N)
                          const float*  __restrict__ weight_sl,   // (S,N)
                          const int*    __restrict__ ind,         // (B,)
                          float*        __restrict__ out)         // (B,N,L)
{
    extern __shared__ char smem[];
    unsigned*       s_xu   = (unsigned*)(smem + S_XH_B);   // bf16 tile as u32
    float*          s_wadj = (float*)(smem + S_WADJ_B);
    float*          s_w    = (float*)(smem + S_W_B);
    float*          s_wsl  = (float*)(smem + S_WSL_B);
    float*          s_bias = (float*)(smem + S_BIAS_B);
    int*            s_rowp = (int*)(smem + S_ROWP_B);
    unsigned short* s_ord  = (unsigned short*)(smem + S_ORD_B);
    unsigned short* s_adjn = (unsigned short*)(smem + S_ADJN_B);

    const int b    = blockIdx.x;
    const int tid  = threadIdx.x;
    const int slot = ind[b];
    const float* __restrict__ xg = inputs + (size_t)b * 2 * N_NODES * LDIM;

    // ---- phase A: stage smem -------------------------------------------
    {   // x -> bf16 tile: 3312 float4 -> uint2
        const float4* src = (const float4*)xg;
        uint2* dst = (uint2*)s_xu;
        #pragma unroll 4
        for (int i = tid; i < (N_NODES * LDIM) / 4; i += 512) {
            const float4 v = src[i];
            __nv_bfloat162 h0 = __floats2bfloat162_rn(v.x, v.y);
            __nv_bfloat162 h1 = __floats2bfloat162_rn(v.z, v.w);
            uint2 p;
            p.x = *reinterpret_cast<unsigned*>(&h0);
            p.y = *reinterpret_cast<unsigned*>(&h1);
            dst[i] = p;
        }
    }
    {
        const float* wrow = weight_diff + (size_t)slot * N_EDGES;
        for (int i = tid; i < 1728; i += 512)
            s_w[i] = (i < N_EDGES) ? wrow[i] : 0.0f;
    }
    for (int i = tid; i < N_NODES; i += 512) {
        s_wsl[i]  = weight_sl[(size_t)slot * N_NODES + i];
        s_bias[i] = bias_diff[(size_t)slot * N_NODES + i];
    }
    for (int i = tid; i < N_SLOTS_PAD + 1; i += 512) s_rowp[i] = g_rowptr4[i];
    for (int i = tid; i < N_SLOTS_PAD / 2; i += 512)
        ((unsigned*)s_ord)[i] = ((const unsigned*)g_order)[i];
    {   // adjacency offsets: 9216 B as 576 uint4
        const uint4* src = (const uint4*)g_adj_node;
        uint4* dst = (uint4*)s_adjn;
        for (int i = tid; i < ADJ_CAP / 8; i += 512) dst[i] = src[i];
    }
    __syncthreads();

    // ---- phase B: expand weights into adjacency order -------------------
    for (int t = tid; t < ADJ_CAP; t += 512)
        s_wadj[t] = s_w[(int)g_adj_edge[t]];
    __syncthreads();

    // ---- phase C: gather --------------------------------------------------
    const int warp = tid >> 5;           // 0..15
    const int lane = tid & 31;
    const int half = lane >> 4;          // 0: slot A, 1: slot B
    const int hl   = lane & 15;          // column group (4 cols) within half

    #pragma unroll 1
    for (int pass = 0; pass < 7; ++pass) {
        const int sl = pass * 32 + warp * 2 + half;     // sorted slot
        const int w  = s_ord[sl];                        // node id (0xFFFF invalid)
        const bool vn = (w != 0xFFFF);
        const int beg = s_rowp[sl];
        const int ng  = (s_rowp[sl + 1] - beg) >> 2;

        // prefetch diagonal x row (fp32, global/L2) — consumed after loop
        float4 xw = make_float4(0.f, 0.f, 0.f, 0.f);
        if (vn) xw = *(const float4*)(xg + w * LDIM + 4 * hl);

        const int ngo = __shfl_xor_sync(0xffffffffu, ng, 16);
        const int ngmax = ng > ngo ? ng : ngo;

        float ax = 0.f, ay = 0.f, az = 0.f, aw = 0.f, deg = 0.f;

        #pragma unroll 1
        for (int g = 0; g < ngmax; ++g) {
            const bool gv = (g < ng);
            const int t = beg + ((gv ? g : 0) << 2);
            const ushort4 of = *(const ushort4*)(s_adjn + t);
            float4 wq = *(const float4*)(s_wadj + t);
            if (!gv) { wq.x = 0.f; wq.y = 0.f; wq.z = 0.f; wq.w = 0.f; }

            uint2 u;
            u = *(const uint2*)(s_xu + of.x + 2 * hl);
            deg += wq.x;
            ax = fmaf(wq.x, __uint_as_float(u.x << 16), ax);
            ay = fmaf(wq.x, __uint_as_float(u.x & 0xffff0000u), ay);
            az = fmaf(wq.x, __uint_as_float(u.y << 16), az);
            aw = fmaf(wq.x, __uint_as_float(u.y & 0xffff0000u), aw);

            u = *(const uint2*)(s_xu + of.y + 2 * hl);
            deg += wq.y;
            ax = fmaf(wq.y, __uint_as_float(u.x << 16), ax);
            ay = fmaf(wq.y, __uint_as_float(u.x & 0xffff0000u), ay);
            az = fmaf(wq.y, __uint_as_float(u.y << 16), az);
            aw = fmaf(wq.y, __uint_as_float(u.y & 0xffff0000u), aw);

            u = *(const uint2*)(s_xu + of.z + 2 * hl);
            deg += wq.z;
            ax = fmaf(wq.z, __uint_as_float(u.x << 16), ax);
            ay = fmaf(wq.z, __uint_as_float(u.x & 0xffff0000u), ay);
            az = fmaf(wq.z, __uint_as_float(u.y << 16), az);
            aw = fmaf(wq.z, __uint_as_float(u.y & 0xffff0000u), aw);

            u = *(const uint2*)(s_xu + of.w + 2 * hl);
            deg += wq.w;
            ax = fmaf(wq.w, __uint_as_float(u.x << 16), ax);
            ay = fmaf(wq.w, __uint_as_float(u.x & 0xffff0000u), ay);
            az = fmaf(wq.w, __uint_as_float(u.y << 16), az);
            aw = fmaf(wq.w, __uint_as_float(u.y & 0xffff0000u), aw);
        }

        if (vn) {
            const float sc = deg + 1.0f + s_wsl[w];
            const float bi = s_bias[w];
            float4 o;
            o.x = fmaf(sc, xw.x, bi - ax);
            o.y = fmaf(sc, xw.y, bi - ay);
            o.z = fmaf(sc, xw.z, bi - az);
            o.w = fmaf(sc, xw.w, bi - aw);
            *(float4*)(out + ((size_t)b * N_NODES + w) * LDIM + 4 * hl) = o;
        }
    }
}

// ---------------- launcher ---------------------------------------------
extern "C" void kernel_launch(void* const* d_in, const int* in_sizes, int n_in,
                              void* d_out, int out_size) {
    const float* inputs      = (const float*)d_in[0];
    const float* weight_diff = (const float*)d_in[1];
    const float* bias_diff   = (const float*)d_in[2];
    const float* weight_sl   = (const float*)d_in[3];
    const int*   ind         = (const int*)d_in[4];
    const int*   edge_i      = (const int*)d_in[5];
    const int*   edge_j      = (const int*)d_in[6];
    float*       out         = (float*)d_out;

    static bool attr_set = false;   // host-side config only, not a work guard
    if (!attr_set) {
        cudaFuncSetAttribute(diffusion_gcn_kernel,
                             cudaFuncAttributeMaxDynamicSharedMemorySize,
                             SMEM_BYTES);
        attr_set = true;
    }

    build_csr_kernel<<<1, 1024>>>(edge_i, edge_j);
    diffusion_gcn_kernel<<<BATCH, 512, SMEM_BYTES>>>(
        inputs, weight_diff, bias_diff, weight_sl, ind, out);
}

// round 5
// speedup vs baseline: 2.1306x; 1.0667x over previous
#include <cuda_runtime.h>
#include <cuda_bf16.h>
#include <cstdint>

#define N_NODES 207
#define N_EDGES 1722
#define LDIM    64
#define BATCH   1024
#define N_SLOTS_PAD 256          // 4 passes * 16 warps * 4 slots
#define ADJ_CAP 5120             // >= 16 * sum_quads(max ng) (see builder)

// ---------------- device-global CSR scratch (no allocs allowed) ------------
__device__ int g_rowptr4[N_SLOTS_PAD + 1];                   // entry start per SORTED SLOT
__device__ unsigned short g_order[N_SLOTS_PAD];              // slot -> node id (0xFFFF invalid)
__device__ __align__(16) unsigned short g_adj_node[ADJ_CAP]; // nbr*32 (u32 index of bf16 row)
__device__ __align__(16) unsigned short g_adj_edge[ADJ_CAP]; // edge idx; N_EDGES = dummy (w=0)

// ---------------- setup kernel: deterministic quad-padded sorted CSR -------
// Nodes sorted desc by ng=ceil(deg/4) (tie asc id). Slots grouped in QUADS
// (4 consecutive sorted slots); every slot in a quad padded to the quad max
// group count -> the main kernel's 4-slots-per-warp loop needs no bounds
// logic. Entry order within a node = fixed function of entry index -> fully
// deterministic. Scatter done in ONE chunk: each lane owns 4 consecutive
// entries, 4 __match_any rounds accumulate per-warp counts, one cross-warp
// scan produces bases.
__global__ __launch_bounds__(1024, 1)
void build_csr_kernel(const int* __restrict__ edge_i,
                      const int* __restrict__ edge_j) {
    __shared__ int s_ei[N_EDGES];
    __shared__ int s_ej[N_EDGES];
    __shared__ int s_ng[N_NODES];
    __shared__ int s_off[N_NODES + 1];          // deg count -> slot entry base
    __shared__ unsigned short s_ord[N_SLOTS_PAD];
    __shared__ int s_wcnt[32][208];
    const int tid  = threadIdx.x;
    const int warp = tid >> 5;
    const int lane = tid & 31;

    for (int i = tid; i < N_EDGES; i += 1024) {
        s_ei[i] = edge_i[i];
        s_ej[i] = edge_j[i];
    }
    for (int v = tid; v < N_NODES + 1; v += 1024) s_off[v] = 0;
    for (int i = tid; i < N_SLOTS_PAD; i += 1024) s_ord[i] = 0xFFFFu;
    for (int t = tid; t < ADJ_CAP; t += 1024) {
        g_adj_node[t] = 0;
        g_adj_edge[t] = (unsigned short)N_EDGES;    // dummy -> weight 0
    }
    for (int i = tid; i < 32 * 208; i += 1024) ((int*)s_wcnt)[i] = 0;
    __syncthreads();

    // degree count (order-independent)
    for (int idx = tid; idx < 2 * N_EDGES; idx += 1024) {
        const int e = idx >> 1;
        atomicAdd(&s_off[(idx & 1) ? s_ej[e] : s_ei[e]], 1);
    }
    __syncthreads();

    if (tid < N_NODES) s_ng[tid] = (s_off[tid] + 3) >> 2;
    __syncthreads();

    // parallel rank sort: desc by ng, tie asc id
    if (tid < N_NODES) {
        const int nv = s_ng[tid];
        int r = 0;
        for (int u = 0; u < N_NODES; ++u) {
            const int nu = s_ng[u];
            r += (nu > nv) || (nu == nv && u < tid);
        }
        s_ord[r] = (unsigned short)tid;
    }
    __syncthreads();

    // quad scan: 64 quads, 2 rounds of 32 (warp 0)
    if (warp == 0) {
        int carryG = 0;                       // in "quad-max groups"
        #pragma unroll
        for (int c = 0; c < 2; ++c) {
            const int q = c * 32 + lane;
            const int a0 = s_ord[4 * q + 0], a1 = s_ord[4 * q + 1];
            const int a2 = s_ord[4 * q + 2], a3 = s_ord[4 * q + 3];
            const int n0 = (a0 != 0xFFFF) ? s_ng[a0] : 0;
            const int n1 = (a1 != 0xFFFF) ? s_ng[a1] : 0;
            const int n2 = (a2 != 0xFFFF) ? s_ng[a2] : 0;
            const int n3 = (a3 != 0xFFFF) ? s_ng[a3] : 0;
            int m = n0 > n1 ? n0 : n1;
            m = m > n2 ? m : n2;
            m = m > n3 ? m : n3;
            int si = m;
            #pragma unroll
            for (int o = 1; o < 32; o <<= 1) {
                const int t = __shfl_up_sync(0xffffffffu, si, o);
                if (lane >= o) si += t;
            }
            const int base = (carryG + si - m) * 16;   // entries
            g_rowptr4[4 * q + 0] = base;
            g_rowptr4[4 * q + 1] = base + 4 * m;
            g_rowptr4[4 * q + 2] = base + 8 * m;
            g_rowptr4[4 * q + 3] = base + 12 * m;
            if (a0 != 0xFFFF) s_off[a0] = base;
            if (a1 != 0xFFFF) s_off[a1] = base + 4 * m;
            if (a2 != 0xFFFF) s_off[a2] = base + 8 * m;
            if (a3 != 0xFFFF) s_off[a3] = base + 12 * m;
            carryG += __shfl_sync(0xffffffffu, si, 31);
        }
        if (lane == 0) g_rowptr4[N_SLOTS_PAD] = carryG * 16;
    }
    __syncthreads();
    for (int i = tid; i < N_SLOTS_PAD; i += 1024) g_order[i] = s_ord[i];

    // single-chunk scatter: 4 sequential rounds per lane
    int myrank[4], myv[4], mynbr[4], mye[4];
    #pragma unroll
    for (int r = 0; r < 4; ++r) {
        const int idx = tid * 4 + r;
        const bool valid = idx < 2 * N_EDGES;
        int v = 207, nbr = 0, e = 0;                // 207 = shared dummy bucket
        if (valid) {
            e = idx >> 1;
            if (idx & 1) { v = s_ej[e]; nbr = s_ei[e]; }
            else         { v = s_ei[e]; nbr = s_ej[e]; }
        }
        const int prefix = s_wcnt[warp][v];
        const unsigned mask = __match_any_sync(0xffffffffu, v);
        const int rin = __popc(mask & ((1u << lane) - 1u));
        myv[r] = v; mynbr[r] = nbr; mye[r] = e;
        myrank[r] = prefix + rin;
        __syncwarp();
        if (lane == (__ffs(mask) - 1)) s_wcnt[warp][v] = prefix + __popc(mask);
        __syncwarp();
    }
    __syncthreads();

    // cross-warp scan per node: counts -> bases
    if (tid < 208) {
        int run = (tid < N_NODES) ? s_off[tid] : 0;
        #pragma unroll
        for (int w2 = 0; w2 < 32; ++w2) {
            const int t = s_wcnt[w2][tid];
            s_wcnt[w2][tid] = run;
            run += t;
        }
    }
    __syncthreads();

    #pragma unroll
    for (int r = 0; r < 4; ++r) {
        const int idx = tid * 4 + r;
        if (idx < 2 * N_EDGES) {
            const int pos = s_wcnt[warp][myv[r]] + myrank[r];
            g_adj_node[pos] = (unsigned short)(mynbr[r] * 32);   // u32 row index
            g_adj_edge[pos] = (unsigned short)mye[r];
        }
    }
}

// ---------------- main kernel: one CTA (512 thr) per batch element ---------
// Warp = 4 sorted slots (quarters, equal padded ng); lane covers 8 columns
// via one uint4 (8 bf16). Per entry: 1 LDS.128 + 8 unpack + 8 FMA + 1 FADD.
// No bounds predication in the inner loop (quad-padded). Diagonal term reads
// fp32 x from global (L2-hot) after the loop -> full precision on the
// dominant term.
#define S_XU_B    0
#define S_WADJ_B  26496
#define S_W_B     46976
#define S_WSL_B   53888
#define S_BIAS_B  54720
#define S_ROWP_B  55552
#define S_ORD_B   56592
#define S_ADJN_B  57104
#define SMEM_BYTES 67344

#define ENTRY(OFv, Wv) do {                                          \
    const uint4 u = *(const uint4*)(sx + (OFv));                     \
    deg += (Wv);                                                     \
    a0 = fmaf((Wv), __uint_as_float(u.x << 16), a0);                 \
    a1 = fmaf((Wv), __uint_as_float(u.x & 0xffff0000u), a1);         \
    a2 = fmaf((Wv), __uint_as_float(u.y << 16), a2);                 \
    a3 = fmaf((Wv), __uint_as_float(u.y & 0xffff0000u), a3);         \
    a4 = fmaf((Wv), __uint_as_float(u.z << 16), a4);                 \
    a5 = fmaf((Wv), __uint_as_float(u.z & 0xffff0000u), a5);         \
    a6 = fmaf((Wv), __uint_as_float(u.w << 16), a6);                 \
    a7 = fmaf((Wv), __uint_as_float(u.w & 0xffff0000u), a7);         \
} while (0)

__global__ __launch_bounds__(512, 3)
void diffusion_gcn_kernel(const float*  __restrict__ inputs,      // (B,2,N,L)
                          const float*  __restrict__ weight_diff, // (S,E)
                          const float*  __restrict__ bias_diff,   // (S,N)
                          const float*  __restrict__ weight_sl,   // (S,N)
                          const int*    __restrict__ ind,         // (B,)
                          float*        __restrict__ out)         // (B,N,L)
{
    extern __shared__ char smem[];
    unsigned*       s_xu   = (unsigned*)(smem + S_XU_B);     // bf16 tile as u32
    float*          s_wadj = (float*)(smem + S_WADJ_B);
    float*          s_w    = (float*)(smem + S_W_B);
    float*          s_wsl  = (float*)(smem + S_WSL_B);
    float*          s_bias = (float*)(smem + S_BIAS_B);
    int*            s_rowp = (int*)(smem + S_ROWP_B);
    unsigned short* s_ord  = (unsigned short*)(smem + S_ORD_B);
    unsigned short* s_adjn = (unsigned short*)(smem + S_ADJN_B);

    const int b    = blockIdx.x;
    const int tid  = threadIdx.x;
    const int slot = ind[b];
    const float* __restrict__ xg = inputs + (size_t)b * 2 * N_NODES * LDIM;

    // ---- phase A: stage smem -------------------------------------------
    {   // x -> bf16 tile: 3312 float4 -> uint2
        const float4* src = (const float4*)xg;
        uint2* dst = (uint2*)s_xu;
        #pragma unroll 4
        for (int i = tid; i < (N_NODES * LDIM) / 4; i += 512) {
            const float4 v = src[i];
            __nv_bfloat162 h0 = __floats2bfloat162_rn(v.x, v.y);
            __nv_bfloat162 h1 = __floats2bfloat162_rn(v.z, v.w);
            uint2 p;
            p.x = *reinterpret_cast<unsigned*>(&h0);
            p.y = *reinterpret_cast<unsigned*>(&h1);
            dst[i] = p;
        }
    }
    {
        const float* wrow = weight_diff + (size_t)slot * N_EDGES;
        for (int i = tid; i < 1728; i += 512)
            s_w[i] = (i < N_EDGES) ? wrow[i] : 0.0f;
    }
    for (int i = tid; i < N_NODES; i += 512) {
        s_wsl[i]  = weight_sl[(size_t)slot * N_NODES + i];
        s_bias[i] = bias_diff[(size_t)slot * N_NODES + i];
    }
    for (int i = tid; i < N_SLOTS_PAD + 1; i += 512) s_rowp[i] = g_rowptr4[i];
    for (int i = tid; i < N_SLOTS_PAD / 2; i += 512)
        ((unsigned*)s_ord)[i] = ((const unsigned*)g_order)[i];
    {   // adjacency offsets: 10240 B as 640 uint4
        const uint4* src = (const uint4*)g_adj_node;
        uint4* dst = (uint4*)s_adjn;
        for (int i = tid; i < ADJ_CAP / 8; i += 512) dst[i] = src[i];
    }
    __syncthreads();

    // ---- phase B: expand weights into adjacency order -------------------
    for (int t = tid; t < ADJ_CAP; t += 512)
        s_wadj[t] = s_w[(int)g_adj_edge[t]];
    __syncthreads();

    // ---- phase C: gather --------------------------------------------------
    const int warp    = tid >> 5;        // 0..15
    const int lane    = tid & 31;
    const int quarter = lane >> 3;       // slot within quad
    const int hl      = lane & 7;        // 8-column group within slot
    const unsigned* sx = s_xu + 4 * hl;

    #pragma unroll 1
    for (int pass = 0; pass < 4; ++pass) {
        const int sl  = pass * 64 + warp * 4 + quarter;
        const int w   = s_ord[sl];
        const int beg = s_rowp[sl];
        const int ng  = (s_rowp[sl + 1] - beg) >> 2;   // uniform across quad

        float a0 = 0.f, a1 = 0.f, a2 = 0.f, a3 = 0.f;
        float a4 = 0.f, a5 = 0.f, a6 = 0.f, a7 = 0.f;
        float deg = 0.f;

        #pragma unroll 1
        for (int g = 0; g < ng; ++g) {
            const int t = beg + (g << 2);
            const ushort4 of = *(const ushort4*)(s_adjn + t);
            const float4  wq = *(const float4*)(s_wadj + t);
            ENTRY(of.x, wq.x);
            ENTRY(of.y, wq.y);
            ENTRY(of.z, wq.z);
            ENTRY(of.w, wq.w);
        }

        if (w != 0xFFFF) {
            const float* xr = xg + w * LDIM + 8 * hl;
            const float4 x0 = *(const float4*)xr;
            const float4 x1 = *(const float4*)(xr + 4);
            const float sc = deg + 1.0f + s_wsl[w];
            const float bi = s_bias[w];
            float4 o0, o1;
            o0.x = fmaf(sc, x0.x, bi - a0);
            o0.y = fmaf(sc, x0.y, bi - a1);
            o0.z = fmaf(sc, x0.z, bi - a2);
            o0.w = fmaf(sc, x0.w, bi - a3);
            o1.x = fmaf(sc, x1.x, bi - a4);
            o1.y = fmaf(sc, x1.y, bi - a5);
            o1.z = fmaf(sc, x1.z, bi - a6);
            o1.w = fmaf(sc, x1.w, bi - a7);
            float* op = out + ((size_t)b * N_NODES + w) * LDIM + 8 * hl;
            *(float4*)op = o0;
            *(float4*)(op + 4) = o1;
        }
    }
}

// ---------------- launcher ---------------------------------------------
extern "C" void kernel_launch(void* const* d_in, const int* in_sizes, int n_in,
                              void* d_out, int out_size) {
    const float* inputs      = (const float*)d_in[0];
    const float* weight_diff = (const float*)d_in[1];
    const float* bias_diff   = (const float*)d_in[2];
    const float* weight_sl   = (const float*)d_in[3];
    const int*   ind         = (const int*)d_in[4];
    const int*   edge_i      = (const int*)d_in[5];
    const int*   edge_j      = (const int*)d_in[6];
    float*       out         = (float*)d_out;

    static bool attr_set = false;   // host-side config only, not a work guard
    if (!attr_set) {
        cudaFuncSetAttribute(diffusion_gcn_kernel,
                             cudaFuncAttributeMaxDynamicSharedMemorySize,
                             SMEM_BYTES);
        attr_set = true;
    }

    build_csr_kernel<<<1, 1024>>>(edge_i, edge_j);
    diffusion_gcn_kernel<<<BATCH, 512, SMEM_BYTES>>>(
        inputs, weight_diff, bias_diff, weight_sl, ind, out);
}

// round 6
// speedup vs baseline: 2.2645x; 1.0628x over previous
#include <cuda_runtime.h>
#include <cuda_bf16.h>
#include <cstdint>

#define N_NODES 207
#define N_EDGES 1722
#define LDIM    64
#define BATCH   1024
#define N_SLOTS_PAD 256          // 4 passes * 16 warps * 4 slots
#define ADJ_CAP 5120             // >= 16 * sum_quads(max ng)

// ---------------- device-global CSR scratch (no allocs allowed) ------------
__device__ int g_rowptr4[N_SLOTS_PAD + 1];                   // entry start per SORTED SLOT
__device__ unsigned short g_order[N_SLOTS_PAD];              // slot -> node id (0xFFFF invalid)
__device__ __align__(16) unsigned short g_adj_node[ADJ_CAP]; // nbr*32 (u32 index of bf16 row)
__device__ __align__(16) unsigned short g_adj_edge[ADJ_CAP]; // edge idx; N_EDGES = dummy (w=0)

// ---------------- setup kernel: deterministic quad-padded sorted CSR -------
__global__ __launch_bounds__(1024, 1)
void build_csr_kernel(const int* __restrict__ edge_i,
                      const int* __restrict__ edge_j) {
    __shared__ int s_ei[N_EDGES];
    __shared__ int s_ej[N_EDGES];
    __shared__ int s_ng[N_NODES];
    __shared__ int s_off[N_NODES + 1];          // deg count -> slot entry base
    __shared__ unsigned short s_ord[N_SLOTS_PAD];
    __shared__ int s_wcnt[32][208];
    const int tid  = threadIdx.x;
    const int warp = tid >> 5;
    const int lane = tid & 31;

    for (int i = tid; i < N_EDGES; i += 1024) {
        s_ei[i] = edge_i[i];
        s_ej[i] = edge_j[i];
    }
    for (int v = tid; v < N_NODES + 1; v += 1024) s_off[v] = 0;
    for (int i = tid; i < N_SLOTS_PAD; i += 1024) s_ord[i] = 0xFFFFu;
    for (int t = tid; t < ADJ_CAP; t += 1024) {
        g_adj_node[t] = 0;
        g_adj_edge[t] = (unsigned short)N_EDGES;    // dummy -> weight 0
    }
    for (int i = tid; i < 32 * 208; i += 1024) ((int*)s_wcnt)[i] = 0;
    __syncthreads();

    // degree count (order-independent)
    for (int idx = tid; idx < 2 * N_EDGES; idx += 1024) {
        const int e = idx >> 1;
        atomicAdd(&s_off[(idx & 1) ? s_ej[e] : s_ei[e]], 1);
    }
    __syncthreads();

    if (tid < N_NODES) s_ng[tid] = (s_off[tid] + 3) >> 2;
    __syncthreads();

    // parallel rank sort: desc by ng, tie asc id
    if (tid < N_NODES) {
        const int nv = s_ng[tid];
        int r = 0;
        for (int u = 0; u < N_NODES; ++u) {
            const int nu = s_ng[u];
            r += (nu > nv) || (nu == nv && u < tid);
        }
        s_ord[r] = (unsigned short)tid;
    }
    __syncthreads();

    // quad scan: 64 quads, 2 rounds of 32 (warp 0)
    if (warp == 0) {
        int carryG = 0;                       // in "quad-max groups"
        #pragma unroll
        for (int c = 0; c < 2; ++c) {
            const int q = c * 32 + lane;
            const int a0 = s_ord[4 * q + 0], a1 = s_ord[4 * q + 1];
            const int a2 = s_ord[4 * q + 2], a3 = s_ord[4 * q + 3];
            const int n0 = (a0 != 0xFFFF) ? s_ng[a0] : 0;
            const int n1 = (a1 != 0xFFFF) ? s_ng[a1] : 0;
            const int n2 = (a2 != 0xFFFF) ? s_ng[a2] : 0;
            const int n3 = (a3 != 0xFFFF) ? s_ng[a3] : 0;
            int m = n0 > n1 ? n0 : n1;
            m = m > n2 ? m : n2;
            m = m > n3 ? m : n3;
            int si = m;
            #pragma unroll
            for (int o = 1; o < 32; o <<= 1) {
                const int t = __shfl_up_sync(0xffffffffu, si, o);
                if (lane >= o) si += t;
            }
            const int base = (carryG + si - m) * 16;   // entries
            g_rowptr4[4 * q + 0] = base;
            g_rowptr4[4 * q + 1] = base + 4 * m;
            g_rowptr4[4 * q + 2] = base + 8 * m;
            g_rowptr4[4 * q + 3] = base + 12 * m;
            if (a0 != 0xFFFF) s_off[a0] = base;
            if (a1 != 0xFFFF) s_off[a1] = base + 4 * m;
            if (a2 != 0xFFFF) s_off[a2] = base + 8 * m;
            if (a3 != 0xFFFF) s_off[a3] = base + 12 * m;
            carryG += __shfl_sync(0xffffffffu, si, 31);
        }
        if (lane == 0) g_rowptr4[N_SLOTS_PAD] = carryG * 16;
    }
    __syncthreads();
    for (int i = tid; i < N_SLOTS_PAD; i += 1024) g_order[i] = s_ord[i];

    // single-chunk scatter: 4 sequential rounds per lane
    int myrank[4], myv[4], mynbr[4], mye[4];
    #pragma unroll
    for (int r = 0; r < 4; ++r) {
        const int idx = tid * 4 + r;
        const bool valid = idx < 2 * N_EDGES;
        int v = 207, nbr = 0, e = 0;                // 207 = shared dummy bucket
        if (valid) {
            e = idx >> 1;
            if (idx & 1) { v = s_ej[e]; nbr = s_ei[e]; }
            else         { v = s_ei[e]; nbr = s_ej[e]; }
        }
        const int prefix = s_wcnt[warp][v];
        const unsigned mask = __match_any_sync(0xffffffffu, v);
        const int rin = __popc(mask & ((1u << lane) - 1u));
        myv[r] = v; mynbr[r] = nbr; mye[r] = e;
        myrank[r] = prefix + rin;
        __syncwarp();
        if (lane == (__ffs(mask) - 1)) s_wcnt[warp][v] = prefix + __popc(mask);
        __syncwarp();
    }
    __syncthreads();

    // cross-warp scan per node: counts -> bases
    if (tid < 208) {
        int run = (tid < N_NODES) ? s_off[tid] : 0;
        #pragma unroll
        for (int w2 = 0; w2 < 32; ++w2) {
            const int t = s_wcnt[w2][tid];
            s_wcnt[w2][tid] = run;
            run += t;
        }
    }
    __syncthreads();

    #pragma unroll
    for (int r = 0; r < 4; ++r) {
        const int idx = tid * 4 + r;
        if (idx < 2 * N_EDGES) {
            const int pos = s_wcnt[warp][myv[r]] + myrank[r];
            g_adj_node[pos] = (unsigned short)(mynbr[r] * 32);   // u32 row index
            g_adj_edge[pos] = (unsigned short)mye[r];
        }
    }
}

// ---------------- main kernel: one CTA (512 thr) per batch element ---------
// Warp = 4 sorted slots (quarters, equal padded ng); lane covers 8 columns.
// Inner loop fully in packed bf16x2: per entry = 1 LDS.128 + 4 HFMA2 +
// SHL/FADD (fp32 deg). Accumulators unpack to fp32 ONCE per pass.
// Diagonal term: fp32 x from global (L2-hot); first half prefetched before
// the gather loop to hide latency.
#define S_XU_B    0
#define S_WADJ_B  26496
#define S_W_B     46976
#define S_WSL_B   53888
#define S_BIAS_B  54720
#define S_ROWP_B  55552
#define S_ORD_B   56592
#define S_ADJN_B  57104
#define SMEM_BYTES 67344

__device__ __forceinline__ __nv_bfloat162 as_bf2(unsigned v) {
    return *reinterpret_cast<__nv_bfloat162*>(&v);
}
__device__ __forceinline__ unsigned as_u32(__nv_bfloat162 v) {
    return *reinterpret_cast<unsigned*>(&v);
}

// 1 LDS.128 + 4 HFMA2 + 1 SHL + 1 FADD per entry
#define ENTRY(OFv, WPv) do {                                          \
    const uint4 u = *(const uint4*)(sx + (OFv));                      \
    const __nv_bfloat162 wb = as_bf2(WPv);                            \
    deg += __uint_as_float((WPv) << 16);                              \
    c0 = __hfma2(wb, as_bf2(u.x), c0);                                \
    c1 = __hfma2(wb, as_bf2(u.y), c1);                                \
    c2 = __hfma2(wb, as_bf2(u.z), c2);                                \
    c3 = __hfma2(wb, as_bf2(u.w), c3);                                \
} while (0)

__global__ __launch_bounds__(512, 3)
void diffusion_gcn_kernel(const float*  __restrict__ inputs,      // (B,2,N,L)
                          const float*  __restrict__ weight_diff, // (S,E)
                          const float*  __restrict__ bias_diff,   // (S,N)
                          const float*  __restrict__ weight_sl,   // (S,N)
                          const int*    __restrict__ ind,         // (B,)
                          float*        __restrict__ out)         // (B,N,L)
{
    extern __shared__ char smem[];
    unsigned*       s_xu    = (unsigned*)(smem + S_XU_B);     // bf16 tile as u32
    unsigned*       s_wadjh = (unsigned*)(smem + S_WADJ_B);   // packed bf16x2 (w,w)
    float*          s_w     = (float*)(smem + S_W_B);
    float*          s_wsl   = (float*)(smem + S_WSL_B);
    float*          s_bias  = (float*)(smem + S_BIAS_B);
    int*            s_rowp  = (int*)(smem + S_ROWP_B);
    unsigned short* s_ord   = (unsigned short*)(smem + S_ORD_B);
    unsigned short* s_adjn  = (unsigned short*)(smem + S_ADJN_B);

    const int b    = blockIdx.x;
    const int tid  = threadIdx.x;
    const int slot = ind[b];
    const float* __restrict__ xg = inputs + (size_t)b * 2 * N_NODES * LDIM;

    // ---- phase A: stage smem -------------------------------------------
    {   // x -> bf16 tile: 3312 float4 -> uint2
        const float4* src = (const float4*)xg;
        uint2* dst = (uint2*)s_xu;
        #pragma unroll 4
        for (int i = tid; i < (N_NODES * LDIM) / 4; i += 512) {
            const float4 v = src[i];
            __nv_bfloat162 h0 = __floats2bfloat162_rn(v.x, v.y);
            __nv_bfloat162 h1 = __floats2bfloat162_rn(v.z, v.w);
            uint2 p;
            p.x = as_u32(h0);
            p.y = as_u32(h1);
            dst[i] = p;
        }
    }
    {
        const float* wrow = weight_diff + (size_t)slot * N_EDGES;
        for (int i = tid; i < 1728; i += 512)
            s_w[i] = (i < N_EDGES) ? wrow[i] : 0.0f;
    }
    for (int i = tid; i < N_NODES; i += 512) {
        s_wsl[i]  = weight_sl[(size_t)slot * N_NODES + i];
        s_bias[i] = bias_diff[(size_t)slot * N_NODES + i];
    }
    for (int i = tid; i < N_SLOTS_PAD + 1; i += 512) s_rowp[i] = g_rowptr4[i];
    for (int i = tid; i < N_SLOTS_PAD / 2; i += 512)
        ((unsigned*)s_ord)[i] = ((const unsigned*)g_order)[i];
    {   // adjacency offsets: 10240 B as 640 uint4
        const uint4* src = (const uint4*)g_adj_node;
        uint4* dst = (uint4*)s_adjn;
        for (int i = tid; i < ADJ_CAP / 8; i += 512) dst[i] = src[i];
    }
    __syncthreads();

    // ---- phase B: expand weights to adjacency order as packed bf16x2 ----
    for (int t = tid; t < ADJ_CAP; t += 512) {
        const float w = s_w[(int)g_adj_edge[t]];
        s_wadjh[t] = as_u32(__float2bfloat162_rn(w));   // replicate (w,w)
    }
    __syncthreads();

    // ---- phase C: gather --------------------------------------------------
    const int warp    = tid >> 5;        // 0..15
    const int lane    = tid & 31;
    const int quarter = lane >> 3;       // slot within quad
    const int hl      = lane & 7;        // 8-column group within slot
    const unsigned* sx = s_xu + 4 * hl;

    #pragma unroll 1
    for (int pass = 0; pass < 4; ++pass) {
        const int sl  = pass * 64 + warp * 4 + quarter;
        const int w   = s_ord[sl];
        const int beg = s_rowp[sl];
        const int ng  = (s_rowp[sl + 1] - beg) >> 2;   // uniform across quad

        // prefetch first half of diagonal fp32 row (hides L2 latency)
        const float* xr = (w != 0xFFFF) ? (xg + w * LDIM + 8 * hl) : xg;
        const float4 x0 = *(const float4*)xr;

        __nv_bfloat162 c0 = as_bf2(0u), c1 = as_bf2(0u);
        __nv_bfloat162 c2 = as_bf2(0u), c3 = as_bf2(0u);
        float deg = 0.f;

        #pragma unroll 1
        for (int g = 0; g < ng; ++g) {
            const int t = beg + (g << 2);
            const ushort4 of = *(const ushort4*)(s_adjn + t);
            const uint4   wp = *(const uint4*)(s_wadjh + t);
            ENTRY(of.x, wp.x);
            ENTRY(of.y, wp.y);
            ENTRY(of.z, wp.z);
            ENTRY(of.w, wp.w);
        }

        if (w != 0xFFFF) {
            const float4 x1 = *(const float4*)(xr + 4);
            // unpack bf16x2 accumulators -> fp32 (once per pass)
            const unsigned r0 = as_u32(c0), r1 = as_u32(c1);
            const unsigned r2 = as_u32(c2), r3 = as_u32(c3);
            const float sc = deg + 1.0f + s_wsl[w];
            const float bi = s_bias[w];
            float4 o0, o1;
            o0.x = fmaf(sc, x0.x, bi - __uint_as_float(r0 << 16));
            o0.y = fmaf(sc, x0.y, bi - __uint_as_float(r0 & 0xffff0000u));
            o0.z = fmaf(sc, x0.z, bi - __uint_as_float(r1 << 16));
            o0.w = fmaf(sc, x0.w, bi - __uint_as_float(r1 & 0xffff0000u));
            o1.x = fmaf(sc, x1.x, bi - __uint_as_float(r2 << 16));
            o1.y = fmaf(sc, x1.y, bi - __uint_as_float(r2 & 0xffff0000u));
            o1.z = fmaf(sc, x1.z, bi - __uint_as_float(r3 << 16));
            o1.w = fmaf(sc, x1.w, bi - __uint_as_float(r3 & 0xffff0000u));
            float* op = out + ((size_t)b * N_NODES + w) * LDIM + 8 * hl;
            *(float4*)op = o0;
            *(float4*)(op + 4) = o1;
        }
    }
}

// ---------------- launcher ---------------------------------------------
extern "C" void kernel_launch(void* const* d_in, const int* in_sizes, int n_in,
                              void* d_out, int out_size) {
    const float* inputs      = (const float*)d_in[0];
    const float* weight_diff = (const float*)d_in[1];
    const float* bias_diff   = (const float*)d_in[2];
    const float* weight_sl   = (const float*)d_in[3];
    const int*   ind         = (const int*)d_in[4];
    const int*   edge_i      = (const int*)d_in[5];
    const int*   edge_j      = (const int*)d_in[6];
    float*       out         = (float*)d_out;

    static bool attr_set = false;   // host-side config only, not a work guard
    if (!attr_set) {
        cudaFuncSetAttribute(diffusion_gcn_kernel,
                             cudaFuncAttributeMaxDynamicSharedMemorySize,
                             SMEM_BYTES);
        attr_set = true;
    }

    build_csr_kernel<<<1, 1024>>>(edge_i, edge_j);
    diffusion_gcn_kernel<<<BATCH, 512, SMEM_BYTES>>>(
        inputs, weight_diff, bias_diff, weight_sl, ind, out);
}